// round 10
// baseline (speedup 1.0000x reference)
#include <cuda_runtime.h>
#include <cuda_bf16.h>
#include <cstdint>

// Problem constants (E=8, R=64, B=4, S=4096, D=2048)
#define E_N   8
#define RNK   64
#define DIM   2048
#define NTOK  16384
#define TM    128
#define NTHR  512

// ---------------- device scratch ----------------
__device__ int g_count[E_N];
__device__ int g_offset[E_N];
__device__ int g_tokens[NTOK];

// ---------------- helpers ----------------
__device__ __forceinline__ uint32_t smem_u32(const void* p) {
    uint32_t a;
    asm("{ .reg .u64 t; cvta.to.shared.u64 t, %1; cvt.u32.u64 %0, t; }" : "=r"(a) : "l"(p));
    return a;
}
__device__ __forceinline__ uint32_t swz(uint32_t o) { return o ^ ((o >> 3) & 0x70); }

// split fp32 pair -> packed bf16 hi-pair + lo-pair
__device__ __forceinline__ void split2(float a, float b, uint32_t& hi, uint32_t& lo) {
    __nv_bfloat16 ha = __float2bfloat16_rn(a), hb = __float2bfloat16_rn(b);
    float ra = a - __bfloat162float(ha), rb = b - __bfloat162float(hb);
    __nv_bfloat16 la = __float2bfloat16_rn(ra), lb = __float2bfloat16_rn(rb);
    hi = ((uint32_t)__bfloat16_as_ushort(hb) << 16) | (uint32_t)__bfloat16_as_ushort(ha);
    lo = ((uint32_t)__bfloat16_as_ushort(lb) << 16) | (uint32_t)__bfloat16_as_ushort(la);
}

__device__ __forceinline__ void ldm_x4(uint32_t a, uint32_t r[4]) {
    asm volatile("ldmatrix.sync.aligned.m8n8.x4.shared.b16 {%0,%1,%2,%3}, [%4];"
                 : "=r"(r[0]), "=r"(r[1]), "=r"(r[2]), "=r"(r[3]) : "r"(a));
}
__device__ __forceinline__ void mma16816(float* c, const uint32_t* a, const uint32_t* b) {
    asm volatile("mma.sync.aligned.m16n8k16.row.col.f32.bf16.bf16.f32 "
                 "{%0,%1,%2,%3}, {%4,%5,%6,%7}, {%8,%9}, {%0,%1,%2,%3};"
                 : "+f"(c[0]), "+f"(c[1]), "+f"(c[2]), "+f"(c[3])
                 : "r"(a[0]), "r"(a[1]), "r"(a[2]), "r"(a[3]), "r"(b[0]), "r"(b[1]));
}

// ---------------- SMEM layout (bytes) ----------------
// 64     : tok[128]
// 1024   : X bufs fp32 (128 rows x 288B stride) 36864 each; X0@1024, X1@37888 (end 74752)
//          Htmp fp32 reduce bufs reuse X region: 128 rows x 264B = 33792;
//            HT0@1024, HT1@34816 (end 68608)
//          stage2 B bufs reuse X region: {Bhi 16K, Blo 16K}=32K; B0@1024, B1@33792
// 74752  : A bufs {Ahi 8K, Alo 8K}=16K; A0@74752, A1@91136 (end 107520)
// 107520 : Hhi 16K ; 123904 : Hlo 16K (end 140288)
#define SM_TOK    64
#define SM_X0     1024
#define X_STRIDE  36864
#define X_ROWB    288
#define SM_HT0    1024
#define SM_HT1    34816
#define HT_ROWB   264
#define SM_B0     1024
#define B_STRIDE  32768
#define SM_A0     74752
#define A_STRIDE  16384
#define SM_HHI    107520
#define SM_HLO    123904
#define SMEM_BYTES 140288

// ---------------- sort kernel (single CTA) ----------------
__global__ void __launch_bounds__(1024) k_sort(const int* __restrict__ ti) {
    __shared__ int sc[E_N];
    __shared__ int sb[E_N];
    const int tid = threadIdx.x;
    const int lane = tid & 31;
    if (tid < E_N) sc[tid] = 0;
    __syncthreads();
    for (int t = tid; t < NTOK; t += 1024) {
        int e = ti[t];
        unsigned mask = __match_any_sync(0xffffffffu, e);
        int leader = __ffs(mask) - 1;
        if (lane == leader) atomicAdd(&sc[e], __popc(mask));
    }
    __syncthreads();
    if (tid == 0) {
        int acc = 0;
        for (int e = 0; e < E_N; ++e) {
            g_count[e] = sc[e];
            g_offset[e] = acc;
            sb[e] = acc;
            acc += sc[e];
        }
    }
    __syncthreads();
    for (int t = tid; t < NTOK; t += 1024) {
        int e = ti[t];
        unsigned mask = __match_any_sync(0xffffffffu, e);
        int leader = __ffs(mask) - 1;
        int prior = __popc(mask & ((1u << lane) - 1));
        int base = 0;
        if (lane == leader) base = atomicAdd(&sb[e], __popc(mask));
        base = __shfl_sync(0xffffffffu, base, leader);
        g_tokens[base + prior] = t;
    }
}

// ---------------- main kernel ----------------
__global__ void __launch_bounds__(NTHR, 1)
k_main(const float* __restrict__ x,
       const float* __restrict__ Aw,
       const float* __restrict__ Bw,
       float* __restrict__ out) {
    const int e = blockIdx.y;
    const int cnt = g_count[e];
    const int mstart = blockIdx.x * TM;
    if (mstart >= cnt) return;
    const int base = g_offset[e];

    extern __shared__ char smc[];
    const uint32_t sbu = smem_u32(smc);
    const int tid = threadIdx.x;
    const int wid = tid >> 5;
    const int lane = tid & 31;
    const int g = lane >> 2;
    const int tq = lane & 3;
    // stage-1 warp tile: m32 x n64 x k16-of-64  (m-split 4 x k-split 4)
    const int s1mg = wid >> 2;   // rows s1mg*32..+32
    const int s1k  = wid & 3;    // k-slice s1k*16..+16 within each 64-chunk
    // stage-2 warp tile: m32 x n32
    const int s2mg = wid >> 2;   // rows s2mg*32..+32
    const int s2ng = wid & 3;    // chunk cols s2ng*32..+32
    int* tok = (int*)(smc + SM_TOK);

    if (tid < TM) {
        int i = mstart + tid;
        tok[tid] = (i < cnt) ? g_tokens[base + i] : -1;
    }
    __syncthreads();

    const float* Arow = Aw + (size_t)e * RNK * DIM;
    const float* Brow = Bw + (size_t)e * DIM * RNK;

    // ldmatrix lane patterns (pre-swizzle, relative to tile row base)
    const uint32_t bpair = (uint32_t)((lane & 7) + ((lane >> 4) << 3)) * 128 +
                           (uint32_t)((lane >> 3) & 1) * 16;          // 16-row n-pair
    const uint32_t apat  = (uint32_t)(lane & 15) * 128 + (uint32_t)(lane >> 4) * 16; // m16 A-op

    // ---- fill mappings (coalesced full 128B lines per LDG instr) ----
    const int xfr = tid >> 3, xfq = tid & 7;
    const int xt0 = tok[xfr], xt1 = tok[xfr + 64];
    const float* xp0 = x + (size_t)(xt0 < 0 ? 0 : xt0) * DIM;
    const float* xp1 = x + (size_t)(xt1 < 0 ? 0 : xt1) * DIM;
    float4 vx[4];
    const int fr = tid >> 3, fq = tid & 7;
    float4 va[2];

#define LOAD_X(K0)                                                              \
    do {                                                                        \
        float4 z = make_float4(0.f, 0.f, 0.f, 0.f);                             \
        vx[0] = (xt0 >= 0) ? *(const float4*)(xp0 + (K0) + xfq * 4) : z;        \
        vx[1] = (xt0 >= 0) ? *(const float4*)(xp0 + (K0) + 32 + xfq * 4) : z;   \
        vx[2] = (xt1 >= 0) ? *(const float4*)(xp1 + (K0) + xfq * 4) : z;        \
        vx[3] = (xt1 >= 0) ? *(const float4*)(xp1 + (K0) + 32 + xfq * 4) : z;   \
    } while (0)

#define STORE_X(BUF)                                                            \
    do {                                                                        \
        char* xb_ = smc + SM_X0 + (BUF) * X_STRIDE;                             \
        *(float4*)(xb_ + xfr * X_ROWB + xfq * 16)              = vx[0];         \
        *(float4*)(xb_ + xfr * X_ROWB + 128 + xfq * 16)        = vx[1];         \
        *(float4*)(xb_ + (xfr + 64) * X_ROWB + xfq * 16)       = vx[2];         \
        *(float4*)(xb_ + (xfr + 64) * X_ROWB + 128 + xfq * 16) = vx[3];         \
    } while (0)

#define LOAD_A(K0)                                                              \
    do {                                                                        \
        _Pragma("unroll") for (int i = 0; i < 2; ++i) va[i] =                   \
            *(const float4*)(Arow + (size_t)fr * DIM + (K0) + fq * 4 + i * 32); \
    } while (0)

#define STORE_A(BUF)                                                            \
    do {                                                                        \
        char* ah = smc + SM_A0 + (BUF) * A_STRIDE;                              \
        char* al = ah + 8192;                                                   \
        _Pragma("unroll") for (int i = 0; i < 2; ++i) {                         \
            uint32_t h0, l0, h1, l1;                                            \
            split2(va[i].x, va[i].y, h0, l0);                                   \
            split2(va[i].z, va[i].w, h1, l1);                                   \
            uint32_t off = swz((uint32_t)fr * 128 + fq * 8 + i * 64);           \
            *(uint2*)(ah + off) = make_uint2(h0, h1);                           \
            *(uint2*)(al + off) = make_uint2(l0, l1);                           \
        }                                                                       \
    } while (0)

    // ===== stage 1: H[128,64] = X[128,2048] * A_e^T =====
    // acc1[mt][j]: rows s1mg*32+mt*16+{g,g+8}, cols j*8+2tq (+1); partial over k
    float acc1[2][8][4];
#pragma unroll
    for (int mt = 0; mt < 2; ++mt)
#pragma unroll
        for (int j = 0; j < 8; ++j)
#pragma unroll
            for (int q = 0; q < 4; ++q) acc1[mt][j][q] = 0.f;

    LOAD_X(0);
    LOAD_A(0);
    STORE_X(0);
    STORE_A(0);
    __syncthreads();
    LOAD_X(64);
    LOAD_A(64);

    // fragment-read offsets within X SMEM tile (per mt, rows g / g+8)
    const uint32_t xo00 = (uint32_t)(s1mg * 32 + g) * X_ROWB + tq * 8 + s1k * 64;
    const uint32_t xo01 = (uint32_t)(s1mg * 32 + 8 + g) * X_ROWB + tq * 8 + s1k * 64;
    const uint32_t xo10 = (uint32_t)(s1mg * 32 + 16 + g) * X_ROWB + tq * 8 + s1k * 64;
    const uint32_t xo11 = (uint32_t)(s1mg * 32 + 24 + g) * X_ROWB + tq * 8 + s1k * 64;

    for (int c = 0; c < 32; ++c) {
        const char* xb = smc + SM_X0 + (c & 1) * X_STRIDE;
        const uint32_t ahB = sbu + SM_A0 + (uint32_t)(c & 1) * A_STRIDE;
        // X fragments for this warp's k-slice
        uint32_t xh[2][4], xl[2][4];
        {
            float2 r0 = *(const float2*)(xb + xo00);
            float2 r1 = *(const float2*)(xb + xo01);
            float2 r2 = *(const float2*)(xb + xo00 + 32);
            float2 r3 = *(const float2*)(xb + xo01 + 32);
            split2(r0.x, r0.y, xh[0][0], xl[0][0]);
            split2(r1.x, r1.y, xh[0][1], xl[0][1]);
            split2(r2.x, r2.y, xh[0][2], xl[0][2]);
            split2(r3.x, r3.y, xh[0][3], xl[0][3]);
            float2 r4 = *(const float2*)(xb + xo10);
            float2 r5 = *(const float2*)(xb + xo11);
            float2 r6 = *(const float2*)(xb + xo10 + 32);
            float2 r7 = *(const float2*)(xb + xo11 + 32);
            split2(r4.x, r4.y, xh[1][0], xl[1][0]);
            split2(r5.x, r5.y, xh[1][1], xl[1][1]);
            split2(r6.x, r6.y, xh[1][2], xl[1][2]);
            split2(r7.x, r7.y, xh[1][3], xl[1][3]);
        }
#pragma unroll
        for (int jj = 0; jj < 4; ++jj) {
            uint32_t bh[4], bl[4];
            uint32_t ao = swz((uint32_t)(jj * 16) * 128 + bpair + s1k * 32);
            ldm_x4(ahB + ao, bh);
            ldm_x4(ahB + 8192 + ao, bl);
#pragma unroll
            for (int mt = 0; mt < 2; ++mt) {
                mma16816(acc1[mt][jj * 2], xh[mt], bh);
                mma16816(acc1[mt][jj * 2], xh[mt], bl);
                mma16816(acc1[mt][jj * 2], xl[mt], bh);
                mma16816(acc1[mt][jj * 2 + 1], xh[mt], bh + 2);
                mma16816(acc1[mt][jj * 2 + 1], xh[mt], bl + 2);
                mma16816(acc1[mt][jj * 2 + 1], xl[mt], bh + 2);
            }
        }
        if (c < 31) {
            STORE_X((c + 1) & 1);
            STORE_A((c + 1) & 1);
            if (c < 30) {
                LOAD_X((c + 2) * 64);
                LOAD_A((c + 2) * 64);
            }
        }
        __syncthreads();
    }

    // ===== stage 2 B fill regs (issue GMEM loads early) =====
    const int bfn = tid >> 3, bfq = tid & 7;
    float4 vb[4];

#define LOAD_B(N0)                                                              \
    do {                                                                        \
        const float* s0 = Brow + (size_t)((N0) + bfn) * RNK + bfq * 4;          \
        const float* s1 = Brow + (size_t)((N0) + bfn + 64) * RNK + bfq * 4;     \
        vb[0] = *(const float4*)(s0);                                           \
        vb[1] = *(const float4*)(s0 + 32);                                      \
        vb[2] = *(const float4*)(s1);                                           \
        vb[3] = *(const float4*)(s1 + 32);                                      \
    } while (0)

#define STORE_B(BUF)                                                            \
    do {                                                                        \
        char* bh_ = smc + SM_B0 + (BUF) * B_STRIDE;                             \
        char* bl_ = bh_ + 16384;                                                \
        _Pragma("unroll") for (int i = 0; i < 4; ++i) {                         \
            uint32_t h0, l0, h1, l1;                                            \
            split2(vb[i].x, vb[i].y, h0, l0);                                   \
            split2(vb[i].z, vb[i].w, h1, l1);                                   \
            uint32_t row = (uint32_t)bfn + (i >> 1) * 64;                       \
            uint32_t off = swz(row * 128 + bfq * 8 + (i & 1) * 64);             \
            *(uint2*)(bh_ + off) = make_uint2(h0, h1);                          \
            *(uint2*)(bl_ + off) = make_uint2(l0, l1);                          \
        }                                                                       \
    } while (0)

    LOAD_B(0);

    // ===== cross-warp k-reduction of acc1 (fp32 tree via Htmp) =====
    // Htmp slot for (row r, col c) = r*HT_ROWB + c*4 (264B stride: conflict-free)
#define HT_ST(HT)                                                               \
    do {                                                                        \
        char* ht_ = smc + (HT);                                                 \
        _Pragma("unroll") for (int mt = 0; mt < 2; ++mt)                        \
        _Pragma("unroll") for (int j = 0; j < 8; ++j) {                         \
            uint32_t r0_ = (uint32_t)(s1mg * 32 + mt * 16 + g);                 \
            uint32_t cb_ = (uint32_t)(j * 8 + 2 * tq) * 4;                      \
            *(float2*)(ht_ + r0_ * HT_ROWB + cb_) =                             \
                make_float2(acc1[mt][j][0], acc1[mt][j][1]);                    \
            *(float2*)(ht_ + (r0_ + 8) * HT_ROWB + cb_) =                       \
                make_float2(acc1[mt][j][2], acc1[mt][j][3]);                    \
        }                                                                       \
    } while (0)

#define HT_ADD(HT)                                                              \
    do {                                                                        \
        char* ht_ = smc + (HT);                                                 \
        _Pragma("unroll") for (int mt = 0; mt < 2; ++mt)                        \
        _Pragma("unroll") for (int j = 0; j < 8; ++j) {                         \
            uint32_t r0_ = (uint32_t)(s1mg * 32 + mt * 16 + g);                 \
            uint32_t cb_ = (uint32_t)(j * 8 + 2 * tq) * 4;                      \
            float2 p0_ = *(const float2*)(ht_ + r0_ * HT_ROWB + cb_);           \
            float2 p1_ = *(const float2*)(ht_ + (r0_ + 8) * HT_ROWB + cb_);     \
            acc1[mt][j][0] += p0_.x; acc1[mt][j][1] += p0_.y;                   \
            acc1[mt][j][2] += p1_.x; acc1[mt][j][3] += p1_.y;                   \
        }                                                                       \
    } while (0)

    if (s1k == 1) HT_ST(SM_HT0);
    if (s1k == 3) HT_ST(SM_HT1);
    __syncthreads();
    if (s1k == 0) HT_ADD(SM_HT0);
    if (s1k == 2) HT_ADD(SM_HT1);
    __syncthreads();
    if (s1k == 2) HT_ST(SM_HT0);
    __syncthreads();
    if (s1k == 0) {
        HT_ADD(SM_HT0);
        // final H -> SMEM bf16 hi/lo (fragment-consistent layout)
        char* hh = smc + SM_HHI;
        char* hl = smc + SM_HLO;
#pragma unroll
        for (int mt = 0; mt < 2; ++mt)
#pragma unroll
            for (int j = 0; j < 8; ++j) {
                int col = j * 8 + 2 * tq;
                int r0 = s1mg * 32 + mt * 16 + g;
                uint32_t hi, lo;
                split2(acc1[mt][j][0], acc1[mt][j][1], hi, lo);
                uint32_t off = swz((uint32_t)r0 * 128 + (uint32_t)col * 2);
                *(uint32_t*)(hh + off) = hi;
                *(uint32_t*)(hl + off) = lo;
                split2(acc1[mt][j][2], acc1[mt][j][3], hi, lo);
                uint32_t off2 = swz((uint32_t)(r0 + 8) * 128 + (uint32_t)col * 2);
                *(uint32_t*)(hh + off2) = hi;
                *(uint32_t*)(hl + off2) = lo;
            }
    }
    __syncthreads();

    STORE_B(0);
    __syncthreads();

    // preload ALL H fragments into registers (reused across all 16 n-chunks)
    uint32_t hfh[2][4][4], hfl[2][4][4];
#pragma unroll
    for (int mt = 0; mt < 2; ++mt)
#pragma unroll
        for (int kk = 0; kk < 4; ++kk) {
            uint32_t ho = swz((uint32_t)(s2mg * 32 + mt * 16) * 128 + apat + kk * 32);
            ldm_x4(sbu + SM_HHI + ho, hfh[mt][kk]);
            ldm_x4(sbu + SM_HLO + ho, hfl[mt][kk]);
        }

    // stage-2 output tokens for this warp
    int tko[2][2];
#pragma unroll
    for (int mt = 0; mt < 2; ++mt) {
        tko[mt][0] = tok[s2mg * 32 + mt * 16 + g];
        tko[mt][1] = tok[s2mg * 32 + mt * 16 + 8 + g];
    }

    LOAD_B(128);

    // ===== stage 2: O[128,2048] = H[128,64] * B_e^T, 16 n-chunks of 128 =====
    for (int nc = 0; nc < 16; ++nc) {
        float acc2[2][4][4];
#pragma unroll
        for (int mt = 0; mt < 2; ++mt)
#pragma unroll
            for (int j = 0; j < 4; ++j)
#pragma unroll
                for (int q = 0; q < 4; ++q) acc2[mt][j][q] = 0.f;

        const uint32_t bbB = sbu + SM_B0 + (uint32_t)(nc & 1) * B_STRIDE;
#pragma unroll
        for (int kk = 0; kk < 4; ++kk) {
#pragma unroll
            for (int jj = 0; jj < 2; ++jj) {
                uint32_t bh[4], bl[4];
                uint32_t bo = swz((uint32_t)(s2ng * 32 + jj * 16) * 128 + bpair + kk * 32);
                ldm_x4(bbB + bo, bh);
                ldm_x4(bbB + 16384 + bo, bl);
#pragma unroll
                for (int mt = 0; mt < 2; ++mt) {
                    mma16816(acc2[mt][jj * 2], hfh[mt][kk], bh);
                    mma16816(acc2[mt][jj * 2], hfh[mt][kk], bl);
                    mma16816(acc2[mt][jj * 2], hfl[mt][kk], bh);
                    mma16816(acc2[mt][jj * 2 + 1], hfh[mt][kk], bh + 2);
                    mma16816(acc2[mt][jj * 2 + 1], hfh[mt][kk], bl + 2);
                    mma16816(acc2[mt][jj * 2 + 1], hfl[mt][kk], bh + 2);
                }
            }
        }

        // epilogue: direct STG.64
        const int nb0 = nc * 128 + s2ng * 32 + 2 * tq;
#pragma unroll
        for (int mt = 0; mt < 2; ++mt)
#pragma unroll
            for (int j = 0; j < 4; ++j) {
                int colo = nb0 + j * 8;
                if (tko[mt][0] >= 0)
                    *(float2*)(out + (size_t)tko[mt][0] * DIM + colo) =
                        make_float2(acc2[mt][j][0], acc2[mt][j][1]);
                if (tko[mt][1] >= 0)
                    *(float2*)(out + (size_t)tko[mt][1] * DIM + colo) =
                        make_float2(acc2[mt][j][2], acc2[mt][j][3]);
            }

        if (nc < 15) {
            STORE_B((nc + 1) & 1);
            if (nc < 14) LOAD_B((nc + 2) * 128);
        }
        __syncthreads();
    }
}

// ---------------- launch ----------------
extern "C" void kernel_launch(void* const* d_in, const int* in_sizes, int n_in,
                              void* d_out, int out_size) {
    const float* x  = (const float*)d_in[0];   // [B,S,D]
    const float* Aw = (const float*)d_in[1];   // [E,R,D]
    const float* Bw = (const float*)d_in[2];   // [E,D,R]
    const int*   ti = (const int*)d_in[3];     // [B,S]
    float* out = (float*)d_out;
    (void)in_sizes; (void)n_in; (void)out_size;

    static int smem_set = 0;
    if (!smem_set) {
        cudaFuncSetAttribute(k_main, cudaFuncAttributeMaxDynamicSharedMemorySize, SMEM_BYTES);
        smem_set = 1;
    }

    k_sort<<<1, 1024>>>(ti);
    dim3 grid(NTOK / TM, E_N, 1);
    k_main<<<grid, NTHR, SMEM_BYTES>>>(x, Aw, Bw, out);
}